// round 4
// baseline (speedup 1.0000x reference)
#include <cuda_runtime.h>
#include <cuda_fp16.h>
#include <cstdint>
#include <math.h>

#define D_MODEL 512
#define N_HEADS 8
#define HEAD_DIM 64
#define BATCH 4
#define SEQ 2048
#define M_TOTAL (BATCH*SEQ)   // 8192

// Scratch: __device__ globals (allocation-guard-safe), referenced directly
// from device code. Q/K/Vt are fp16 (written by projections), ctx is fp32.
__device__ __half g_Q  [BATCH*SEQ*D_MODEL];   // [B,S,D]   pre-scaled by 1/8
__device__ __half g_K  [BATCH*SEQ*D_MODEL];   // [B,S,D]
__device__ __half g_Vt [BATCH*SEQ*D_MODEL];   // [B,H,hd,SK] (pre-transposed V)
__device__ float  g_ctx[BATCH*SEQ*D_MODEL];   // [B,S,D]

__device__ __forceinline__ void mma16(float* d, const uint32_t* a, const uint32_t* b){
    asm volatile(
        "mma.sync.aligned.m16n8k16.row.col.f32.f16.f16.f32 "
        "{%0,%1,%2,%3},{%4,%5,%6,%7},{%8,%9},{%0,%1,%2,%3};"
        : "+f"(d[0]), "+f"(d[1]), "+f"(d[2]), "+f"(d[3])
        : "r"(a[0]), "r"(a[1]), "r"(a[2]), "r"(a[3]), "r"(b[0]), "r"(b[1]));
}
__device__ __forceinline__ void ldsm4(uint32_t* r, uint32_t a){
    asm volatile("ldmatrix.sync.aligned.m8n8.x4.shared.b16 {%0,%1,%2,%3},[%4];"
        : "=r"(r[0]), "=r"(r[1]), "=r"(r[2]), "=r"(r[3]) : "r"(a));
}
__device__ __forceinline__ void stsm4(uint32_t a, uint32_t r0, uint32_t r1,
                                      uint32_t r2, uint32_t r3){
    asm volatile("stmatrix.sync.aligned.m8n8.x4.shared.b16 [%0],{%1,%2,%3,%4};"
        :: "r"(a), "r"(r0), "r"(r1), "r"(r2), "r"(r3));
}
__device__ __forceinline__ uint32_t h2u(float a, float b){
    __half2 h = __floats2half2_rn(a, b); return *(uint32_t*)&h;
}
__device__ __forceinline__ float gelu_exact(float x){
    return 0.5f * x * (1.0f + erff(x * 0.70710678118654752f));
}

// ---------------------------------------------------------------------------
// GEMM tile body: C[8192,512] = act(A) @ W^T + bias, fp16 mma + ldmatrix.
// mode 0: C=g_Q fp16 (scaled 1/8)   mode 1: C=g_K fp16
// mode 2: C=g_Vt fp16 transposed    mode 3: A=g_ctx+GELU, C=Cout fp32
// Tile 128x64, k-tile 64, 256 thr, warp grid 4(m) x 2(n), warp tile 32x32.
// ---------------------------------------------------------------------------
__device__ __forceinline__ void gemm_tile(
    const float* __restrict__ A, const float* __restrict__ W,
    const float* __restrict__ bias, int mode, float* __restrict__ Cout)
{
    __shared__ __align__(16) __half sA[128][72];
    __shared__ __align__(16) __half sB[64][72];

    const int tid = threadIdx.x, lane = tid & 31, wrp = tid >> 5;
    const int wm = wrp & 3, wn = wrp >> 2;
    const int g = lane >> 2, tg = lane & 3;
    const int m0 = blockIdx.y * 128, n0 = blockIdx.x * 64;

    const uint32_t aA = (uint32_t)__cvta_generic_to_shared(&sA[0][0]);
    const uint32_t aB = (uint32_t)__cvta_generic_to_shared(&sB[0][0]);
    // ldmatrix per-lane bases (pitch 72 halves = 144B)
    const uint32_t baseA = ((wm*32 + ((lane>>3)&1)*8 + (lane&7))*72 + (lane>>4)*8)*2;
    const uint32_t baseB = ((wn*32 + (lane>>4)*8 + (lane&7))*72 + ((lane>>3)&1)*8)*2;

    float acc[2][4][4];
    #pragma unroll
    for (int mi = 0; mi < 2; mi++)
        #pragma unroll
        for (int nj = 0; nj < 4; nj++)
            #pragma unroll
            for (int k = 0; k < 4; k++) acc[mi][nj][k] = 0.f;

    float4 pa[8], pb[4];
    #pragma unroll
    for (int i = 0; i < 8; i++) {
        int id = tid + i * 256, r = id >> 4, c4 = (id & 15) << 2;
        pa[i] = *(const float4*)(A + (size_t)(m0 + r) * D_MODEL + c4);
    }
    #pragma unroll
    for (int i = 0; i < 4; i++) {
        int id = tid + i * 256, r = id >> 4, c4 = (id & 15) << 2;
        pb[i] = *(const float4*)(W + (size_t)(n0 + r) * D_MODEL + c4);
    }

    for (int it = 0; it < 8; it++) {
        __syncthreads();
        #pragma unroll
        for (int i = 0; i < 8; i++) {
            int id = tid + i * 256, r = id >> 4, c4 = (id & 15) << 2;
            float4 v = pa[i];
            if (mode == 3) {
                v.x = gelu_exact(v.x); v.y = gelu_exact(v.y);
                v.z = gelu_exact(v.z); v.w = gelu_exact(v.w);
            }
            *(__half2*)&sA[r][c4]     = __floats2half2_rn(v.x, v.y);
            *(__half2*)&sA[r][c4 + 2] = __floats2half2_rn(v.z, v.w);
        }
        #pragma unroll
        for (int i = 0; i < 4; i++) {
            int id = tid + i * 256, r = id >> 4, c4 = (id & 15) << 2;
            float4 v = pb[i];
            *(__half2*)&sB[r][c4]     = __floats2half2_rn(v.x, v.y);
            *(__half2*)&sB[r][c4 + 2] = __floats2half2_rn(v.z, v.w);
        }
        __syncthreads();

        if (it < 7) {
            int k0 = (it + 1) * 64;
            #pragma unroll
            for (int i = 0; i < 8; i++) {
                int id = tid + i * 256, r = id >> 4, c4 = (id & 15) << 2;
                pa[i] = *(const float4*)(A + (size_t)(m0 + r) * D_MODEL + k0 + c4);
            }
            #pragma unroll
            for (int i = 0; i < 4; i++) {
                int id = tid + i * 256, r = id >> 4, c4 = (id & 15) << 2;
                pb[i] = *(const float4*)(W + (size_t)(n0 + r) * D_MODEL + k0 + c4);
            }
        }

        #pragma unroll
        for (int kk = 0; kk < 4; kk++) {
            uint32_t af[2][4], bf[2][4];
            ldsm4(af[0], aA + baseA + (kk * 16) * 2);
            ldsm4(af[1], aA + baseA + (16 * 72 + kk * 16) * 2);
            ldsm4(bf[0], aB + baseB + (kk * 16) * 2);
            ldsm4(bf[1], aB + baseB + (16 * 72 + kk * 16) * 2);
            #pragma unroll
            for (int mi = 0; mi < 2; mi++) {
                mma16(acc[mi][0], af[mi], bf[0] + 0);
                mma16(acc[mi][1], af[mi], bf[0] + 2);
                mma16(acc[mi][2], af[mi], bf[1] + 0);
                mma16(acc[mi][3], af[mi], bf[1] + 2);
            }
        }
    }

    #pragma unroll
    for (int mi = 0; mi < 2; mi++)
        #pragma unroll
        for (int nj = 0; nj < 4; nj++) {
            int col0 = n0 + wn * 32 + nj * 8 + tg * 2;
            float bz0 = bias[col0], bz1 = bias[col0 + 1];
            #pragma unroll
            for (int half = 0; half < 2; half++) {
                int row = m0 + wm * 32 + mi * 16 + g + half * 8;
                float v0 = acc[mi][nj][half * 2 + 0] + bz0;
                float v1 = acc[mi][nj][half * 2 + 1] + bz1;
                if (mode == 0) {
                    *(__half2*)&g_Q[(size_t)row * D_MODEL + col0] =
                        __floats2half2_rn(v0 * 0.125f, v1 * 0.125f);
                } else if (mode == 1) {
                    *(__half2*)&g_K[(size_t)row * D_MODEL + col0] = __floats2half2_rn(v0, v1);
                } else if (mode == 2) {
                    int bb = row >> 11, s = row & 2047;
                    g_Vt[((size_t)(bb * D_MODEL + col0    )) * SEQ + s] = __float2half_rn(v0);
                    g_Vt[((size_t)(bb * D_MODEL + col0 + 1)) * SEQ + s] = __float2half_rn(v1);
                } else {
                    float2 v; v.x = v0; v.y = v1;
                    *(float2*)&Cout[(size_t)row * D_MODEL + col0] = v;
                }
            }
        }
}

// QKV fused: blockIdx.z selects projection (cuts launch count + wave tails)
__global__ __launch_bounds__(256) void qkv_kernel(
    const float* __restrict__ query, const float* __restrict__ key,
    const float* __restrict__ value,
    const float* __restrict__ Wq, const float* __restrict__ bq,
    const float* __restrict__ Wk, const float* __restrict__ bk,
    const float* __restrict__ Wv, const float* __restrict__ bv)
{
    int mode = blockIdx.z;
    const float* A = (mode == 0) ? query : (mode == 1) ? key : value;
    const float* W = (mode == 0) ? Wq : (mode == 1) ? Wk : Wv;
    const float* b = (mode == 0) ? bq : (mode == 1) ? bk : bv;
    gemm_tile(A, W, b, mode, nullptr);
}

__global__ __launch_bounds__(256) void out_kernel(
    const float* __restrict__ Wo, const float* __restrict__ bo,
    float* __restrict__ Cout)
{
    gemm_tile((const float*)g_ctx, Wo, bo, 3, Cout);
}

// ---------------------------------------------------------------------------
// Flash attention (fp16 mma + ldmatrix/stmatrix): grid (SQ/64, B*H), 128 thr.
// ---------------------------------------------------------------------------
__global__ __launch_bounds__(128) void attn_kernel()
{
    __shared__ __align__(16) __half sKP[64][72];  // K tile [kv][d]; reused as P [q][kv]
    __shared__ __align__(16) __half sV [64][72];  // V^T tile [d][kv]

    const int tid = threadIdx.x, lane = tid & 31, wrp = tid >> 5;
    const int g = lane >> 2, tg = lane & 3;
    const int qb = blockIdx.x, bh = blockIdx.y, b = bh >> 3, h = bh & 7;

    const __half* Qp = g_Q + (size_t)(b * SEQ + qb * 64) * D_MODEL + h * HEAD_DIM;
    const __half* Kp = g_K + (size_t)b * SEQ * D_MODEL + h * HEAD_DIM;
    const __half* Vp = g_Vt + (size_t)bh * HEAD_DIM * SEQ;

    const uint32_t aKP = (uint32_t)__cvta_generic_to_shared(&sKP[0][0]);
    const uint32_t aV  = (uint32_t)__cvta_generic_to_shared(&sV[0][0]);
    // B-operand base: rows = n (lane&7), k-col group = (lane>>3)*8
    const uint32_t bB = ((lane & 7) * 72 + (lane >> 3) * 8) * 2;
    // A-operand / stmatrix base: row = wrp*16 + ((lane>>3)&1)*8 + (lane&7),
    // colh = (lane>>4)*8
    const uint32_t bA = ((wrp * 16 + ((lane >> 3) & 1) * 8 + (lane & 7)) * 72
                        + (lane >> 4) * 8) * 2;

    // Q fragments (loaded once from gmem; already scaled by 1/8)
    uint32_t qf[4][4];
    {
        const int qr = wrp * 16 + g;
        const uint32_t* q0 = (const uint32_t*)(Qp + (size_t)qr * D_MODEL);
        const uint32_t* q1 = (const uint32_t*)(Qp + (size_t)(qr + 8) * D_MODEL);
        #pragma unroll
        for (int kk = 0; kk < 4; kk++) {
            qf[kk][0] = q0[kk * 8 + tg];     qf[kk][1] = q1[kk * 8 + tg];
            qf[kk][2] = q0[kk * 8 + tg + 4]; qf[kk][3] = q1[kk * 8 + tg + 4];
        }
    }

    float O[8][4];
    #pragma unroll
    for (int j = 0; j < 8; j++)
        #pragma unroll
        for (int k = 0; k < 4; k++) O[j][k] = 0.f;
    float mrow0 = -1e30f, mrow1 = -1e30f, lrow0 = 0.f, lrow1 = 0.f;

    #pragma unroll 1
    for (int t = 0; t < SEQ / 64; t++) {
        __syncthreads();
        const __half* Kt  = Kp + (size_t)t * 64 * D_MODEL;
        const __half* Vtt = Vp + t * 64;
        #pragma unroll
        for (int i = 0; i < 4; i++) {
            int id = tid + i * 128;
            int r = id >> 3, c = (id & 7) << 3;
            *(uint4*)&sKP[r][c] = *(const uint4*)(Kt + (size_t)r * D_MODEL + c);
            *(uint4*)&sV[r][c]  = *(const uint4*)(Vtt + (size_t)r * SEQ + c);
        }
        __syncthreads();

        // S = Q' K^T : 16 ldmatrix.x4 + 32 mma
        float S[8][4];
        #pragma unroll
        for (int j = 0; j < 8; j++) {
            uint32_t sb[8];
            ldsm4(sb,     aKP + bB + (j * 8 * 72) * 2);
            ldsm4(sb + 4, aKP + bB + (j * 8 * 72 + 32) * 2);
            #pragma unroll
            for (int k = 0; k < 4; k++) S[j][k] = 0.f;
            mma16(S[j], qf[0], sb + 0);
            mma16(S[j], qf[1], sb + 2);
            mma16(S[j], qf[2], sb + 4);
            mma16(S[j], qf[3], sb + 6);
        }

        // online softmax (rows g, g+8; cols partitioned across the quad)
        float tm0 = -1e30f, tm1 = -1e30f;
        #pragma unroll
        for (int j = 0; j < 8; j++) {
            tm0 = fmaxf(tm0, fmaxf(S[j][0], S[j][1]));
            tm1 = fmaxf(tm1, fmaxf(S[j][2], S[j][3]));
        }
        tm0 = fmaxf(tm0, __shfl_xor_sync(0xffffffffu, tm0, 1));
        tm0 = fmaxf(tm0, __shfl_xor_sync(0xffffffffu, tm0, 2));
        tm1 = fmaxf(tm1, __shfl_xor_sync(0xffffffffu, tm1, 1));
        tm1 = fmaxf(tm1, __shfl_xor_sync(0xffffffffu, tm1, 2));
        float mn0 = fmaxf(mrow0, tm0), mn1 = fmaxf(mrow1, tm1);
        float sc0 = __expf(mrow0 - mn0), sc1 = __expf(mrow1 - mn1);
        mrow0 = mn0; mrow1 = mn1;
        float rs0 = 0.f, rs1 = 0.f;
        #pragma unroll
        for (int j = 0; j < 8; j++) {
            S[j][0] = __expf(S[j][0] - mn0); S[j][1] = __expf(S[j][1] - mn0);
            rs0 += S[j][0] + S[j][1];
            S[j][2] = __expf(S[j][2] - mn1); S[j][3] = __expf(S[j][3] - mn1);
            rs1 += S[j][2] + S[j][3];
        }
        lrow0 = lrow0 * sc0 + rs0;
        lrow1 = lrow1 * sc1 + rs1;
        #pragma unroll
        for (int j = 0; j < 8; j++) {
            O[j][0] *= sc0; O[j][1] *= sc0; O[j][2] *= sc1; O[j][3] *= sc1;
        }

        __syncthreads();   // all warps done reading K tile before P overwrites it
        // P writeback: 4 stmatrix.x4 (C-frag layout == A-frag layout on reload)
        #pragma unroll
        for (int jp = 0; jp < 4; jp++) {
            stsm4(aKP + bA + jp * 32,
                  h2u(S[2*jp][0],   S[2*jp][1]),   h2u(S[2*jp][2],   S[2*jp][3]),
                  h2u(S[2*jp+1][0], S[2*jp+1][1]), h2u(S[2*jp+1][2], S[2*jp+1][3]));
        }
        __syncwarp();      // warp reloads only its own 16 rows

        // O += P V : 4 + 16 ldmatrix.x4 + 32 mma
        uint32_t pa[4][4];
        #pragma unroll
        for (int kk = 0; kk < 4; kk++)
            ldsm4(pa[kk], aKP + bA + kk * 32);
        #pragma unroll
        for (int j = 0; j < 8; j++) {
            uint32_t vb[8];
            ldsm4(vb,     aV + bB + (j * 8 * 72) * 2);
            ldsm4(vb + 4, aV + bB + (j * 8 * 72 + 32) * 2);
            mma16(O[j], pa[0], vb + 0);
            mma16(O[j], pa[1], vb + 2);
            mma16(O[j], pa[2], vb + 4);
            mma16(O[j], pa[3], vb + 6);
        }
    }

    // finalize
    lrow0 += __shfl_xor_sync(0xffffffffu, lrow0, 1);
    lrow0 += __shfl_xor_sync(0xffffffffu, lrow0, 2);
    lrow1 += __shfl_xor_sync(0xffffffffu, lrow1, 1);
    lrow1 += __shfl_xor_sync(0xffffffffu, lrow1, 2);
    float inv0 = 1.f / lrow0, inv1 = 1.f / lrow1;

    const int r0 = b * SEQ + qb * 64 + wrp * 16 + g;
    #pragma unroll
    for (int j = 0; j < 8; j++) {
        int col = h * HEAD_DIM + j * 8 + tg * 2;
        float2 v0; v0.x = O[j][0] * inv0; v0.y = O[j][1] * inv0;
        float2 v1; v1.x = O[j][2] * inv1; v1.y = O[j][3] * inv1;
        *(float2*)&g_ctx[(size_t)(r0    ) * D_MODEL + col] = v0;
        *(float2*)&g_ctx[(size_t)(r0 + 8) * D_MODEL + col] = v1;
    }
}

// ---------------------------------------------------------------------------
extern "C" void kernel_launch(void* const* d_in, const int* in_sizes, int n_in,
                              void* d_out, int out_size)
{
    const float* query = (const float*)d_in[0];
    const float* key   = (const float*)d_in[1];
    const float* value = (const float*)d_in[2];
    const float* Wq    = (const float*)d_in[3];
    const float* bq    = (const float*)d_in[4];
    const float* Wk    = (const float*)d_in[5];
    const float* bk    = (const float*)d_in[6];
    const float* Wv    = (const float*)d_in[7];
    const float* bv    = (const float*)d_in[8];
    const float* Wo    = (const float*)d_in[9];
    const float* bo    = (const float*)d_in[10];
    float* out = (float*)d_out;

    qkv_kernel<<<dim3(D_MODEL / 64, M_TOTAL / 128, 3), 256>>>(
        query, key, value, Wq, bq, Wk, bk, Wv, bv);
    attn_kernel<<<dim3(SEQ / 64, BATCH * N_HEADS), 128>>>();
    out_kernel<<<dim3(D_MODEL / 64, M_TOTAL / 128), 256>>>(Wo, bo, out);
}

// round 5
// speedup vs baseline: 1.3958x; 1.3958x over previous
#include <cuda_runtime.h>
#include <cuda_fp16.h>
#include <cstdint>
#include <math.h>

#define D_MODEL 512
#define N_HEADS 8
#define HEAD_DIM 64
#define BATCH 4
#define SEQ 2048
#define M_TOTAL (BATCH*SEQ)   // 8192

// Scratch: __device__ globals (allocation-guard-safe), referenced directly.
__device__ __align__(16) __half g_Qin[M_TOTAL*D_MODEL];   // fp16 copies of inputs
__device__ __align__(16) __half g_Kin[M_TOTAL*D_MODEL];
__device__ __align__(16) __half g_Vin[M_TOTAL*D_MODEL];
__device__ __align__(16) __half g_Wh [4][D_MODEL*D_MODEL]; // Wq,Wk,Wv,Wo fp16
__device__ __align__(16) __half g_Q  [M_TOTAL*D_MODEL];   // [B,S,D] pre-scaled 1/8
__device__ __align__(16) __half g_K  [M_TOTAL*D_MODEL];   // [B,S,D]
__device__ __align__(16) __half g_Vt [M_TOTAL*D_MODEL];   // [B,H,hd,SK]
__device__ __align__(16) __half g_ctxh[M_TOTAL*D_MODEL];  // gelu(ctx) fp16

__device__ __forceinline__ void mma16(float* d, const uint32_t* a, const uint32_t* b){
    asm volatile(
        "mma.sync.aligned.m16n8k16.row.col.f32.f16.f16.f32 "
        "{%0,%1,%2,%3},{%4,%5,%6,%7},{%8,%9},{%0,%1,%2,%3};"
        : "+f"(d[0]), "+f"(d[1]), "+f"(d[2]), "+f"(d[3])
        : "r"(a[0]), "r"(a[1]), "r"(a[2]), "r"(a[3]), "r"(b[0]), "r"(b[1]));
}
__device__ __forceinline__ void ldsm4(uint32_t* r, uint32_t a){
    asm volatile("ldmatrix.sync.aligned.m8n8.x4.shared.b16 {%0,%1,%2,%3},[%4];"
        : "=r"(r[0]), "=r"(r[1]), "=r"(r[2]), "=r"(r[3]) : "r"(a));
}
__device__ __forceinline__ void cp16(uint32_t dst, const void* src){
    asm volatile("cp.async.cg.shared.global [%0], [%1], 16;" :: "r"(dst), "l"(src));
}
__device__ __forceinline__ void cp_commit(){ asm volatile("cp.async.commit_group;"); }
__device__ __forceinline__ float gelu_exact(float x){
    return 0.5f * x * (1.0f + erff(x * 0.70710678118654752f));
}

// ---------------------------------------------------------------------------
// Prep: fp32 -> fp16 conversions (bandwidth-bound, ~14us total)
// ---------------------------------------------------------------------------
__global__ __launch_bounds__(256) void prep_in(
    const float* __restrict__ q, const float* __restrict__ k,
    const float* __restrict__ v)
{
    int z = blockIdx.z;
    const float* src = (z == 0) ? q : (z == 1) ? k : v;
    __half* dst = (z == 0) ? g_Qin : (z == 1) ? g_Kin : g_Vin;
    int i = (blockIdx.x * 256 + threadIdx.x) * 4;       // 4M elems, grid.x=4096
    float4 x = *(const float4*)(src + i);
    __half2 h0 = __floats2half2_rn(x.x, x.y), h1 = __floats2half2_rn(x.z, x.w);
    uint2 u; u.x = *(uint32_t*)&h0; u.y = *(uint32_t*)&h1;
    *(uint2*)(dst + i) = u;
}

__global__ __launch_bounds__(256) void prep_w(
    const float* __restrict__ wq, const float* __restrict__ wk,
    const float* __restrict__ wv, const float* __restrict__ wo)
{
    int z = blockIdx.z;
    const float* src = (z == 0) ? wq : (z == 1) ? wk : (z == 2) ? wv : wo;
    __half* dst = g_Wh[z];
    int i = (blockIdx.x * 256 + threadIdx.x) * 4;       // 256K elems, grid.x=256
    float4 x = *(const float4*)(src + i);
    __half2 h0 = __floats2half2_rn(x.x, x.y), h1 = __floats2half2_rn(x.z, x.w);
    uint2 u; u.x = *(uint32_t*)&h0; u.y = *(uint32_t*)&h1;
    *(uint2*)(dst + i) = u;
}

// ---------------------------------------------------------------------------
// fp16 GEMM, cp.async double-buffered: C[8192,512] = A @ W^T + bias
// Tile 128x64, BK=32, 2 stages, 256 thr, warp grid 4(m)x2(n), warp tile 32x32.
// mode 0: C=g_Q fp16 scaled 1/8   mode 1: C=g_K fp16
// mode 2: C=g_Vt fp16 transposed  mode 3: C=Cout fp32
// ---------------------------------------------------------------------------
__device__ __forceinline__ void gemm16(
    const __half* __restrict__ A, const __half* __restrict__ W,
    const float* __restrict__ bias, int mode, float* __restrict__ Cout)
{
    __shared__ __align__(16) __half sA[2][128][40];   // pitch 40 halves (80B)
    __shared__ __align__(16) __half sB[2][64][40];

    const int tid = threadIdx.x, lane = tid & 31, wrp = tid >> 5;
    const int wm = wrp & 3, wn = wrp >> 2;
    const int g = lane >> 2, tg = lane & 3;
    const int m0 = blockIdx.y * 128, n0 = blockIdx.x * 64;

    const uint32_t aA = (uint32_t)__cvta_generic_to_shared(&sA[0][0][0]);
    const uint32_t aB = (uint32_t)__cvta_generic_to_shared(&sB[0][0][0]);
    const uint32_t ASZ = 128 * 40 * 2, BSZ = 64 * 40 * 2;
    const uint32_t baseA = ((wm*32 + ((lane>>3)&1)*8 + (lane&7))*40 + (lane>>4)*8)*2;
    const uint32_t baseB = ((wn*32 + (lane>>4)*8 + (lane&7))*40 + ((lane>>3)&1)*8)*2;

    // per-thread copy coords: A 512 chunks (2/thr), B 256 chunks (1/thr)
    const int ar0 = tid >> 2, ac = (tid & 3) * 8;          // + second chunk at +64 rows? no:
    // ids: id = tid and tid+256; r=id>>2 in 0..127, c=(id&3)*8
    const int ar1 = (tid + 256) >> 2;
    const int br = tid >> 2, bc = (tid & 3) * 8;           // r 0..63

    float acc[2][4][4];
    #pragma unroll
    for (int mi = 0; mi < 2; mi++)
        #pragma unroll
        for (int nj = 0; nj < 4; nj++)
            #pragma unroll
            for (int k = 0; k < 4; k++) acc[mi][nj][k] = 0.f;

    // stage 0 loads
    {
        cp16(aA + (ar0 * 40 + ac) * 2, A + (size_t)(m0 + ar0) * D_MODEL + ac);
        cp16(aA + (ar1 * 40 + ac) * 2, A + (size_t)(m0 + ar1) * D_MODEL + ac);
        cp16(aB + (br  * 40 + bc) * 2, W + (size_t)(n0 + br ) * D_MODEL + bc);
        cp_commit();
    }

    for (int it = 0; it < 16; it++) {
        if (it < 15) {
            int k0 = (it + 1) * 32;
            uint32_t s = ((it + 1) & 1);
            cp16(aA + s * ASZ + (ar0 * 40 + ac) * 2, A + (size_t)(m0 + ar0) * D_MODEL + k0 + ac);
            cp16(aA + s * ASZ + (ar1 * 40 + ac) * 2, A + (size_t)(m0 + ar1) * D_MODEL + k0 + ac);
            cp16(aB + s * BSZ + (br  * 40 + bc) * 2, W + (size_t)(n0 + br ) * D_MODEL + k0 + bc);
            cp_commit();
            asm volatile("cp.async.wait_group 1;");
        } else {
            asm volatile("cp.async.wait_group 0;");
        }
        __syncthreads();
        const uint32_t s = it & 1;
        #pragma unroll
        for (int kk = 0; kk < 2; kk++) {
            uint32_t af[2][4], bf[2][4];
            ldsm4(af[0], aA + s * ASZ + baseA + kk * 32);
            ldsm4(af[1], aA + s * ASZ + baseA + 16 * 80 + kk * 32);
            ldsm4(bf[0], aB + s * BSZ + baseB + kk * 32);
            ldsm4(bf[1], aB + s * BSZ + baseB + 16 * 80 + kk * 32);
            #pragma unroll
            for (int mi = 0; mi < 2; mi++) {
                mma16(acc[mi][0], af[mi], bf[0] + 0);
                mma16(acc[mi][1], af[mi], bf[0] + 2);
                mma16(acc[mi][2], af[mi], bf[1] + 0);
                mma16(acc[mi][3], af[mi], bf[1] + 2);
            }
        }
        __syncthreads();
    }

    #pragma unroll
    for (int mi = 0; mi < 2; mi++)
        #pragma unroll
        for (int nj = 0; nj < 4; nj++) {
            int col0 = n0 + wn * 32 + nj * 8 + tg * 2;
            float bz0 = bias[col0], bz1 = bias[col0 + 1];
            #pragma unroll
            for (int half = 0; half < 2; half++) {
                int row = m0 + wm * 32 + mi * 16 + g + half * 8;
                float v0 = acc[mi][nj][half * 2 + 0] + bz0;
                float v1 = acc[mi][nj][half * 2 + 1] + bz1;
                if (mode == 0) {
                    *(__half2*)&g_Q[(size_t)row * D_MODEL + col0] =
                        __floats2half2_rn(v0 * 0.125f, v1 * 0.125f);
                } else if (mode == 1) {
                    *(__half2*)&g_K[(size_t)row * D_MODEL + col0] = __floats2half2_rn(v0, v1);
                } else if (mode == 2) {
                    int bb = row >> 11, ss = row & 2047;
                    g_Vt[((size_t)(bb * D_MODEL + col0    )) * SEQ + ss] = __float2half_rn(v0);
                    g_Vt[((size_t)(bb * D_MODEL + col0 + 1)) * SEQ + ss] = __float2half_rn(v1);
                } else {
                    float2 v; v.x = v0; v.y = v1;
                    *(float2*)&Cout[(size_t)row * D_MODEL + col0] = v;
                }
            }
        }
}

__global__ __launch_bounds__(256) void qkv_kernel(
    const float* __restrict__ bq, const float* __restrict__ bk,
    const float* __restrict__ bv)
{
    int mode = blockIdx.z;
    const __half* A = (mode == 0) ? g_Qin : (mode == 1) ? g_Kin : g_Vin;
    const float* b = (mode == 0) ? bq : (mode == 1) ? bk : bv;
    gemm16(A, g_Wh[mode], b, mode, nullptr);
}

__global__ __launch_bounds__(256) void out_kernel(
    const float* __restrict__ bo, float* __restrict__ Cout)
{
    gemm16(g_ctxh, g_Wh[3], bo, 3, Cout);
}

// ---------------------------------------------------------------------------
// Flash attention — R3's measured-good structure (scalar LDS fragment loads).
// Epilogue applies exact GELU and writes fp16 g_ctxh.
// grid (SQ/64, B*H), 128 threads, warp owns 16 q rows.
// ---------------------------------------------------------------------------
__global__ __launch_bounds__(128) void attn_kernel()
{
    __shared__ __half sKP[64][72];   // K tile [kv][d]; reused as P tile [q][kv]
    __shared__ __half sV [64][72];   // V^T tile [d][kv]

    const int tid = threadIdx.x, lane = tid & 31, wrp = tid >> 5;
    const int g = lane >> 2, tg = lane & 3;
    const int qb = blockIdx.x, bh = blockIdx.y, b = bh >> 3, h = bh & 7;

    const __half* Qp = g_Q + (size_t)(b * SEQ + qb * 64) * D_MODEL + h * HEAD_DIM;
    const __half* Kp = g_K + (size_t)b * SEQ * D_MODEL + h * HEAD_DIM;
    const __half* Vp = g_Vt + (size_t)bh * HEAD_DIM * SEQ;

    uint32_t qf[4][4];
    const int qr = wrp * 16 + g;
    {
        const uint32_t* q0 = (const uint32_t*)(Qp + (size_t)qr * D_MODEL);
        const uint32_t* q1 = (const uint32_t*)(Qp + (size_t)(qr + 8) * D_MODEL);
        #pragma unroll
        for (int kk = 0; kk < 4; kk++) {
            qf[kk][0] = q0[kk * 8 + tg];     qf[kk][1] = q1[kk * 8 + tg];
            qf[kk][2] = q0[kk * 8 + tg + 4]; qf[kk][3] = q1[kk * 8 + tg + 4];
        }
    }

    float O[8][4];
    #pragma unroll
    for (int j = 0; j < 8; j++)
        #pragma unroll
        for (int k = 0; k < 4; k++) O[j][k] = 0.f;
    float mrow0 = -1e30f, mrow1 = -1e30f, lrow0 = 0.f, lrow1 = 0.f;

    #pragma unroll 1
    for (int t = 0; t < SEQ / 64; t++) {
        __syncthreads();
        const __half* Kt  = Kp + (size_t)t * 64 * D_MODEL;
        const __half* Vtt = Vp + t * 64;
        #pragma unroll
        for (int i = 0; i < 4; i++) {
            int id = tid + i * 128;
            int r = id >> 3, c = (id & 7) << 3;
            *(uint4*)&sKP[r][c] = *(const uint4*)(Kt + (size_t)r * D_MODEL + c);
            *(uint4*)&sV[r][c]  = *(const uint4*)(Vtt + (size_t)r * SEQ + c);
        }
        __syncthreads();

        float S[8][4];
        #pragma unroll
        for (int j = 0; j < 8; j++)
            #pragma unroll
            for (int k = 0; k < 4; k++) S[j][k] = 0.f;
        #pragma unroll
        for (int kk = 0; kk < 4; kk++) {
            #pragma unroll
            for (int j = 0; j < 8; j++) {
                const uint32_t* rb = (const uint32_t*)&sKP[j * 8 + g][0];
                uint32_t bf[2];
                bf[0] = rb[kk * 8 + tg]; bf[1] = rb[kk * 8 + tg + 4];
                mma16(S[j], qf[kk], bf);
            }
        }

        float tm0 = -1e30f, tm1 = -1e30f;
        #pragma unroll
        for (int j = 0; j < 8; j++) {
            tm0 = fmaxf(tm0, fmaxf(S[j][0], S[j][1]));
            tm1 = fmaxf(tm1, fmaxf(S[j][2], S[j][3]));
        }
        tm0 = fmaxf(tm0, __shfl_xor_sync(0xffffffffu, tm0, 1));
        tm0 = fmaxf(tm0, __shfl_xor_sync(0xffffffffu, tm0, 2));
        tm1 = fmaxf(tm1, __shfl_xor_sync(0xffffffffu, tm1, 1));
        tm1 = fmaxf(tm1, __shfl_xor_sync(0xffffffffu, tm1, 2));
        float mn0 = fmaxf(mrow0, tm0), mn1 = fmaxf(mrow1, tm1);
        float sc0 = __expf(mrow0 - mn0), sc1 = __expf(mrow1 - mn1);
        mrow0 = mn0; mrow1 = mn1;
        float rs0 = 0.f, rs1 = 0.f;
        #pragma unroll
        for (int j = 0; j < 8; j++) {
            S[j][0] = __expf(S[j][0] - mn0); S[j][1] = __expf(S[j][1] - mn0);
            rs0 += S[j][0] + S[j][1];
            S[j][2] = __expf(S[j][2] - mn1); S[j][3] = __expf(S[j][3] - mn1);
            rs1 += S[j][2] + S[j][3];
        }
        lrow0 = lrow0 * sc0 + rs0;
        lrow1 = lrow1 * sc1 + rs1;
        #pragma unroll
        for (int j = 0; j < 8; j++) {
            O[j][0] *= sc0; O[j][1] *= sc0; O[j][2] *= sc1; O[j][3] *= sc1;
        }

        __syncthreads();
        const int pr = wrp * 16 + g;
        #pragma unroll
        for (int j = 0; j < 8; j++) {
            *(__half2*)&sKP[pr    ][j * 8 + tg * 2] = __floats2half2_rn(S[j][0], S[j][1]);
            *(__half2*)&sKP[pr + 8][j * 8 + tg * 2] = __floats2half2_rn(S[j][2], S[j][3]);
        }
        __syncwarp();

        #pragma unroll
        for (int kk = 0; kk < 4; kk++) {
            const uint32_t* p0 = (const uint32_t*)&sKP[pr][0];
            const uint32_t* p1 = (const uint32_t*)&sKP[pr + 8][0];
            uint32_t pa[4];
            pa[0] = p0[kk * 8 + tg];     pa[1] = p1[kk * 8 + tg];
            pa[2] = p0[kk * 8 + tg + 4]; pa[3] = p1[kk * 8 + tg + 4];
            #pragma unroll
            for (int j = 0; j < 8; j++) {
                const uint32_t* rb = (const uint32_t*)&sV[j * 8 + g][0];
                uint32_t bf[2];
                bf[0] = rb[kk * 8 + tg]; bf[1] = rb[kk * 8 + tg + 4];
                mma16(O[j], pa, bf);
            }
        }
    }

    lrow0 += __shfl_xor_sync(0xffffffffu, lrow0, 1);
    lrow0 += __shfl_xor_sync(0xffffffffu, lrow0, 2);
    lrow1 += __shfl_xor_sync(0xffffffffu, lrow1, 1);
    lrow1 += __shfl_xor_sync(0xffffffffu, lrow1, 2);
    float inv0 = 1.f / lrow0, inv1 = 1.f / lrow1;

    const int r0 = b * SEQ + qb * 64 + wrp * 16 + g;
    #pragma unroll
    for (int j = 0; j < 8; j++) {
        int col = h * HEAD_DIM + j * 8 + tg * 2;
        float a0 = gelu_exact(O[j][0] * inv0), a1 = gelu_exact(O[j][1] * inv0);
        float b0 = gelu_exact(O[j][2] * inv1), b1 = gelu_exact(O[j][3] * inv1);
        *(__half2*)&g_ctxh[(size_t)(r0    ) * D_MODEL + col] = __floats2half2_rn(a0, a1);
        *(__half2*)&g_ctxh[(size_t)(r0 + 8) * D_MODEL + col] = __floats2half2_rn(b0, b1);
    }
}

// ---------------------------------------------------------------------------
extern "C" void kernel_launch(void* const* d_in, const int* in_sizes, int n_in,
                              void* d_out, int out_size)
{
    const float* query = (const float*)d_in[0];
    const float* key   = (const float*)d_in[1];
    const float* value = (const float*)d_in[2];
    const float* Wq    = (const float*)d_in[3];
    const float* bq    = (const float*)d_in[4];
    const float* Wk    = (const float*)d_in[5];
    const float* bk    = (const float*)d_in[6];
    const float* Wv    = (const float*)d_in[7];
    const float* bv    = (const float*)d_in[8];
    const float* Wo    = (const float*)d_in[9];
    const float* bo    = (const float*)d_in[10];
    float* out = (float*)d_out;

    prep_in<<<dim3(M_TOTAL * D_MODEL / 1024, 1, 3), 256>>>(query, key, value);
    prep_w <<<dim3(D_MODEL * D_MODEL / 1024, 1, 4), 256>>>(Wq, Wk, Wv, Wo);
    qkv_kernel<<<dim3(D_MODEL / 64, M_TOTAL / 128, 3), 256>>>(bq, bk, bv);
    attn_kernel<<<dim3(SEQ / 64, BATCH * N_HEADS), 128>>>();
    out_kernel<<<dim3(D_MODEL / 64, M_TOTAL / 128), 256>>>(bo, out);
}

// round 6
// speedup vs baseline: 1.5229x; 1.0910x over previous
#include <cuda_runtime.h>
#include <cuda_fp16.h>
#include <cstdint>
#include <math.h>

#define D_MODEL 512
#define N_HEADS 8
#define HEAD_DIM 64
#define BATCH 4
#define SEQ 2048
#define M_TOTAL (BATCH*SEQ)   // 8192

// Scratch: __device__ globals (allocation-guard-safe), referenced directly.
__device__ __align__(16) __half g_Qin[M_TOTAL*D_MODEL];   // fp16 copies of inputs
__device__ __align__(16) __half g_Kin[M_TOTAL*D_MODEL];
__device__ __align__(16) __half g_Vin[M_TOTAL*D_MODEL];
__device__ __align__(16) __half g_Wh [4][D_MODEL*D_MODEL]; // Wq,Wk,Wv,Wo fp16
__device__ __align__(16) __half g_Q  [M_TOTAL*D_MODEL];   // [B,S,D] pre-scaled 1/8
__device__ __align__(16) __half g_K  [M_TOTAL*D_MODEL];   // [B,S,D]
__device__ __align__(16) __half g_Vt [M_TOTAL*D_MODEL];   // [B,H,hd,SK]
__device__ __align__(16) __half g_ctxh[M_TOTAL*D_MODEL];  // gelu(ctx) fp16

__device__ __forceinline__ void mma16(float* d, const uint32_t* a, const uint32_t* b){
    asm volatile(
        "mma.sync.aligned.m16n8k16.row.col.f32.f16.f16.f32 "
        "{%0,%1,%2,%3},{%4,%5,%6,%7},{%8,%9},{%0,%1,%2,%3};"
        : "+f"(d[0]), "+f"(d[1]), "+f"(d[2]), "+f"(d[3])
        : "r"(a[0]), "r"(a[1]), "r"(a[2]), "r"(a[3]), "r"(b[0]), "r"(b[1]));
}
__device__ __forceinline__ void ldsm4(uint32_t* r, uint32_t a){
    asm volatile("ldmatrix.sync.aligned.m8n8.x4.shared.b16 {%0,%1,%2,%3},[%4];"
        : "=r"(r[0]), "=r"(r[1]), "=r"(r[2]), "=r"(r[3]) : "r"(a));
}
__device__ __forceinline__ void cp16(uint32_t dst, const void* src){
    asm volatile("cp.async.cg.shared.global [%0], [%1], 16;" :: "r"(dst), "l"(src));
}
__device__ __forceinline__ void cp_commit(){ asm volatile("cp.async.commit_group;"); }
__device__ __forceinline__ uint32_t h2u(float a, float b){
    __half2 h = __floats2half2_rn(a, b); return *(uint32_t*)&h;
}
__device__ __forceinline__ float gelu_exact(float x){
    return 0.5f * x * (1.0f + erff(x * 0.70710678118654752f));
}

// ---------------------------------------------------------------------------
// Prep: fp32 -> fp16 conversions (bandwidth-bound)
// ---------------------------------------------------------------------------
__global__ __launch_bounds__(256) void prep_in(
    const float* __restrict__ q, const float* __restrict__ k,
    const float* __restrict__ v)
{
    int z = blockIdx.z;
    const float* src = (z == 0) ? q : (z == 1) ? k : v;
    __half* dst = (z == 0) ? g_Qin : (z == 1) ? g_Kin : g_Vin;
    int i = (blockIdx.x * 256 + threadIdx.x) * 4;
    float4 x = *(const float4*)(src + i);
    __half2 h0 = __floats2half2_rn(x.x, x.y), h1 = __floats2half2_rn(x.z, x.w);
    uint2 u; u.x = *(uint32_t*)&h0; u.y = *(uint32_t*)&h1;
    *(uint2*)(dst + i) = u;
}

__global__ __launch_bounds__(256) void prep_w(
    const float* __restrict__ wq, const float* __restrict__ wk,
    const float* __restrict__ wv, const float* __restrict__ wo)
{
    int z = blockIdx.z;
    const float* src = (z == 0) ? wq : (z == 1) ? wk : (z == 2) ? wv : wo;
    __half* dst = g_Wh[z];
    int i = (blockIdx.x * 256 + threadIdx.x) * 4;
    float4 x = *(const float4*)(src + i);
    __half2 h0 = __floats2half2_rn(x.x, x.y), h1 = __floats2half2_rn(x.z, x.w);
    uint2 u; u.x = *(uint32_t*)&h0; u.y = *(uint32_t*)&h1;
    *(uint2*)(dst + i) = u;
}

// ---------------------------------------------------------------------------
// fp16 GEMM, cp.async double-buffered (measured-good R5 config, unchanged)
// ---------------------------------------------------------------------------
__device__ __forceinline__ void gemm16(
    const __half* __restrict__ A, const __half* __restrict__ W,
    const float* __restrict__ bias, int mode, float* __restrict__ Cout)
{
    __shared__ __align__(16) __half sA[2][128][40];
    __shared__ __align__(16) __half sB[2][64][40];

    const int tid = threadIdx.x, lane = tid & 31, wrp = tid >> 5;
    const int wm = wrp & 3, wn = wrp >> 2;
    const int g = lane >> 2, tg = lane & 3;
    const int m0 = blockIdx.y * 128, n0 = blockIdx.x * 64;

    const uint32_t aA = (uint32_t)__cvta_generic_to_shared(&sA[0][0][0]);
    const uint32_t aB = (uint32_t)__cvta_generic_to_shared(&sB[0][0][0]);
    const uint32_t ASZ = 128 * 40 * 2, BSZ = 64 * 40 * 2;
    const uint32_t baseA = ((wm*32 + ((lane>>3)&1)*8 + (lane&7))*40 + (lane>>4)*8)*2;
    const uint32_t baseB = ((wn*32 + (lane>>4)*8 + (lane&7))*40 + ((lane>>3)&1)*8)*2;

    const int ar0 = tid >> 2, ac = (tid & 3) * 8;
    const int ar1 = (tid + 256) >> 2;
    const int br = tid >> 2, bc = (tid & 3) * 8;

    float acc[2][4][4];
    #pragma unroll
    for (int mi = 0; mi < 2; mi++)
        #pragma unroll
        for (int nj = 0; nj < 4; nj++)
            #pragma unroll
            for (int k = 0; k < 4; k++) acc[mi][nj][k] = 0.f;

    cp16(aA + (ar0 * 40 + ac) * 2, A + (size_t)(m0 + ar0) * D_MODEL + ac);
    cp16(aA + (ar1 * 40 + ac) * 2, A + (size_t)(m0 + ar1) * D_MODEL + ac);
    cp16(aB + (br  * 40 + bc) * 2, W + (size_t)(n0 + br ) * D_MODEL + bc);
    cp_commit();

    for (int it = 0; it < 16; it++) {
        if (it < 15) {
            int k0 = (it + 1) * 32;
            uint32_t s = ((it + 1) & 1);
            cp16(aA + s * ASZ + (ar0 * 40 + ac) * 2, A + (size_t)(m0 + ar0) * D_MODEL + k0 + ac);
            cp16(aA + s * ASZ + (ar1 * 40 + ac) * 2, A + (size_t)(m0 + ar1) * D_MODEL + k0 + ac);
            cp16(aB + s * BSZ + (br  * 40 + bc) * 2, W + (size_t)(n0 + br ) * D_MODEL + k0 + bc);
            cp_commit();
            asm volatile("cp.async.wait_group 1;");
        } else {
            asm volatile("cp.async.wait_group 0;");
        }
        __syncthreads();
        const uint32_t s = it & 1;
        #pragma unroll
        for (int kk = 0; kk < 2; kk++) {
            uint32_t af[2][4], bf[2][4];
            ldsm4(af[0], aA + s * ASZ + baseA + kk * 32);
            ldsm4(af[1], aA + s * ASZ + baseA + 16 * 80 + kk * 32);
            ldsm4(bf[0], aB + s * BSZ + baseB + kk * 32);
            ldsm4(bf[1], aB + s * BSZ + baseB + 16 * 80 + kk * 32);
            #pragma unroll
            for (int mi = 0; mi < 2; mi++) {
                mma16(acc[mi][0], af[mi], bf[0] + 0);
                mma16(acc[mi][1], af[mi], bf[0] + 2);
                mma16(acc[mi][2], af[mi], bf[1] + 0);
                mma16(acc[mi][3], af[mi], bf[1] + 2);
            }
        }
        __syncthreads();
    }

    #pragma unroll
    for (int mi = 0; mi < 2; mi++)
        #pragma unroll
        for (int nj = 0; nj < 4; nj++) {
            int col0 = n0 + wn * 32 + nj * 8 + tg * 2;
            float bz0 = bias[col0], bz1 = bias[col0 + 1];
            #pragma unroll
            for (int half = 0; half < 2; half++) {
                int row = m0 + wm * 32 + mi * 16 + g + half * 8;
                float v0 = acc[mi][nj][half * 2 + 0] + bz0;
                float v1 = acc[mi][nj][half * 2 + 1] + bz1;
                if (mode == 0) {
                    *(__half2*)&g_Q[(size_t)row * D_MODEL + col0] =
                        __floats2half2_rn(v0 * 0.125f, v1 * 0.125f);
                } else if (mode == 1) {
                    *(__half2*)&g_K[(size_t)row * D_MODEL + col0] = __floats2half2_rn(v0, v1);
                } else if (mode == 2) {
                    int bb = row >> 11, ss = row & 2047;
                    g_Vt[((size_t)(bb * D_MODEL + col0    )) * SEQ + ss] = __float2half_rn(v0);
                    g_Vt[((size_t)(bb * D_MODEL + col0 + 1)) * SEQ + ss] = __float2half_rn(v1);
                } else {
                    float2 v; v.x = v0; v.y = v1;
                    *(float2*)&Cout[(size_t)row * D_MODEL + col0] = v;
                }
            }
        }
}

__global__ __launch_bounds__(256) void qkv_kernel(
    const float* __restrict__ bq, const float* __restrict__ bk,
    const float* __restrict__ bv)
{
    int mode = blockIdx.z;
    const __half* A = (mode == 0) ? g_Qin : (mode == 1) ? g_Kin : g_Vin;
    const float* b = (mode == 0) ? bq : (mode == 1) ? bk : bv;
    gemm16(A, g_Wh[mode], b, mode, nullptr);
}

__global__ __launch_bounds__(256) void out_kernel(
    const float* __restrict__ bo, float* __restrict__ Cout)
{
    gemm16(g_ctxh, g_Wh[3], bo, 3, Cout);
}

// ---------------------------------------------------------------------------
// Flash attention v3: register-resident P (S C-frags ARE PV A-frags) +
// cp.async double-buffered K/V tiles. ONE barrier per KV tile.
// grid (SQ/64, B*H), 128 threads, warp owns 16 q rows.
// ---------------------------------------------------------------------------
__global__ __launch_bounds__(128) void attn_kernel()
{
    __shared__ __align__(16) __half sK[2][64][72];
    __shared__ __align__(16) __half sV[2][64][72];

    const int tid = threadIdx.x, lane = tid & 31, wrp = tid >> 5;
    const int g = lane >> 2, tg = lane & 3;
    const int qb = blockIdx.x, bh = blockIdx.y, b = bh >> 3, h = bh & 7;

    const __half* Qp = g_Q + (size_t)(b * SEQ + qb * 64) * D_MODEL + h * HEAD_DIM;
    const __half* Kp = g_K + (size_t)b * SEQ * D_MODEL + h * HEAD_DIM;
    const __half* Vp = g_Vt + (size_t)bh * HEAD_DIM * SEQ;

    const uint32_t aK = (uint32_t)__cvta_generic_to_shared(&sK[0][0][0]);
    const uint32_t aV = (uint32_t)__cvta_generic_to_shared(&sV[0][0][0]);
    const uint32_t TSZ = 64 * 72 * 2;   // 9216B per stage

    // per-thread async-copy coords: 512 x 16B chunks per tile, 4 per thread
    // id = tid + i*128 ; r = id>>3 (0..63), c = (id&7)*8 halves
    // Q fragments (loaded once; pre-scaled by 1/8)
    uint32_t qf[4][4];
    {
        const int qr = wrp * 16 + g;
        const uint32_t* q0 = (const uint32_t*)(Qp + (size_t)qr * D_MODEL);
        const uint32_t* q1 = (const uint32_t*)(Qp + (size_t)(qr + 8) * D_MODEL);
        #pragma unroll
        for (int kk = 0; kk < 4; kk++) {
            qf[kk][0] = q0[kk * 8 + tg];     qf[kk][1] = q1[kk * 8 + tg];
            qf[kk][2] = q0[kk * 8 + tg + 4]; qf[kk][3] = q1[kk * 8 + tg + 4];
        }
    }

    // prefetch tile 0 into stage 0
    #pragma unroll
    for (int i = 0; i < 4; i++) {
        int id = tid + i * 128, r = id >> 3, c = (id & 7) << 3;
        cp16(aK + (r * 72 + c) * 2, Kp + (size_t)r * D_MODEL + c);
        cp16(aV + (r * 72 + c) * 2, Vp + (size_t)r * SEQ + c);
    }
    cp_commit();

    float O[8][4];
    #pragma unroll
    for (int j = 0; j < 8; j++)
        #pragma unroll
        for (int k = 0; k < 4; k++) O[j][k] = 0.f;
    float mrow0 = -1e30f, mrow1 = -1e30f, lrow0 = 0.f, lrow1 = 0.f;

    #pragma unroll 1
    for (int t = 0; t < SEQ / 64; t++) {
        asm volatile("cp.async.wait_group 0;");
        __syncthreads();   // tile t visible to all; tile t-1 stage reusable

        if (t < SEQ / 64 - 1) {   // issue copy of tile t+1 into the other stage
            const __half* Kt  = Kp + (size_t)(t + 1) * 64 * D_MODEL;
            const __half* Vtt = Vp + (t + 1) * 64;
            const uint32_t s1 = ((t + 1) & 1) * TSZ;
            #pragma unroll
            for (int i = 0; i < 4; i++) {
                int id = tid + i * 128, r = id >> 3, c = (id & 7) << 3;
                cp16(aK + s1 + (r * 72 + c) * 2, Kt + (size_t)r * D_MODEL + c);
                cp16(aV + s1 + (r * 72 + c) * 2, Vtt + (size_t)r * SEQ + c);
            }
            cp_commit();
        }

        const __half (*sKt)[72] = sK[t & 1];
        const __half (*sVt)[72] = sV[t & 1];

        // S = Q' K^T : warp computes 16 x 64
        float S[8][4];
        #pragma unroll
        for (int j = 0; j < 8; j++)
            #pragma unroll
            for (int k = 0; k < 4; k++) S[j][k] = 0.f;
        #pragma unroll
        for (int kk = 0; kk < 4; kk++) {
            #pragma unroll
            for (int j = 0; j < 8; j++) {
                const uint32_t* rb = (const uint32_t*)&sKt[j * 8 + g][0];
                uint32_t bf[2];
                bf[0] = rb[kk * 8 + tg]; bf[1] = rb[kk * 8 + tg + 4];
                mma16(S[j], qf[kk], bf);
            }
        }

        // online softmax (rows g, g+8; cols partitioned across the quad)
        float tm0 = -1e30f, tm1 = -1e30f;
        #pragma unroll
        for (int j = 0; j < 8; j++) {
            tm0 = fmaxf(tm0, fmaxf(S[j][0], S[j][1]));
            tm1 = fmaxf(tm1, fmaxf(S[j][2], S[j][3]));
        }
        tm0 = fmaxf(tm0, __shfl_xor_sync(0xffffffffu, tm0, 1));
        tm0 = fmaxf(tm0, __shfl_xor_sync(0xffffffffu, tm0, 2));
        tm1 = fmaxf(tm1, __shfl_xor_sync(0xffffffffu, tm1, 1));
        tm1 = fmaxf(tm1, __shfl_xor_sync(0xffffffffu, tm1, 2));
        float mn0 = fmaxf(mrow0, tm0), mn1 = fmaxf(mrow1, tm1);
        float sc0 = __expf(mrow0 - mn0), sc1 = __expf(mrow1 - mn1);
        mrow0 = mn0; mrow1 = mn1;
        float rs0 = 0.f, rs1 = 0.f;
        #pragma unroll
        for (int j = 0; j < 8; j++) {
            S[j][0] = __expf(S[j][0] - mn0); S[j][1] = __expf(S[j][1] - mn0);
            rs0 += S[j][0] + S[j][1];
            S[j][2] = __expf(S[j][2] - mn1); S[j][3] = __expf(S[j][3] - mn1);
            rs1 += S[j][2] + S[j][3];
        }
        lrow0 = lrow0 * sc0 + rs0;
        lrow1 = lrow1 * sc1 + rs1;
        #pragma unroll
        for (int j = 0; j < 8; j++) {
            O[j][0] *= sc0; O[j][1] *= sc0; O[j][2] *= sc1; O[j][3] *= sc1;
        }

        // O += P V with P directly from S registers:
        // C-frag of S (block j) == A-frag (halves) for kv-block kk = j/2.
        #pragma unroll
        for (int kk = 0; kk < 4; kk++) {
            uint32_t pa[4];
            pa[0] = h2u(S[2*kk    ][0], S[2*kk    ][1]);   // row g,   kv 16kk+2tg
            pa[1] = h2u(S[2*kk    ][2], S[2*kk    ][3]);   // row g+8
            pa[2] = h2u(S[2*kk + 1][0], S[2*kk + 1][1]);   // row g,   kv 16kk+8+2tg
            pa[3] = h2u(S[2*kk + 1][2], S[2*kk + 1][3]);   // row g+8
            #pragma unroll
            for (int j = 0; j < 8; j++) {
                const uint32_t* rb = (const uint32_t*)&sVt[j * 8 + g][0];
                uint32_t bf[2];
                bf[0] = rb[kk * 8 + tg]; bf[1] = rb[kk * 8 + tg + 4];
                mma16(O[j], pa, bf);
            }
        }
    }

    // finalize: row sums across quad, normalize, GELU, write fp16 ctx
    lrow0 += __shfl_xor_sync(0xffffffffu, lrow0, 1);
    lrow0 += __shfl_xor_sync(0xffffffffu, lrow0, 2);
    lrow1 += __shfl_xor_sync(0xffffffffu, lrow1, 1);
    lrow1 += __shfl_xor_sync(0xffffffffu, lrow1, 2);
    float inv0 = 1.f / lrow0, inv1 = 1.f / lrow1;

    const int r0 = b * SEQ + qb * 64 + wrp * 16 + g;
    #pragma unroll
    for (int j = 0; j < 8; j++) {
        int col = h * HEAD_DIM + j * 8 + tg * 2;
        float a0 = gelu_exact(O[j][0] * inv0), a1 = gelu_exact(O[j][1] * inv0);
        float b0 = gelu_exact(O[j][2] * inv1), b1 = gelu_exact(O[j][3] * inv1);
        *(__half2*)&g_ctxh[(size_t)(r0    ) * D_MODEL + col] = __floats2half2_rn(a0, a1);
        *(__half2*)&g_ctxh[(size_t)(r0 + 8) * D_MODEL + col] = __floats2half2_rn(b0, b1);
    }
}

// ---------------------------------------------------------------------------
extern "C" void kernel_launch(void* const* d_in, const int* in_sizes, int n_in,
                              void* d_out, int out_size)
{
    const float* query = (const float*)d_in[0];
    const float* key   = (const float*)d_in[1];
    const float* value = (const float*)d_in[2];
    const float* Wq    = (const float*)d_in[3];
    const float* bq    = (const float*)d_in[4];
    const float* Wk    = (const float*)d_in[5];
    const float* bk    = (const float*)d_in[6];
    const float* Wv    = (const float*)d_in[7];
    const float* bv    = (const float*)d_in[8];
    const float* Wo    = (const float*)d_in[9];
    const float* bo    = (const float*)d_in[10];
    float* out = (float*)d_out;

    prep_in<<<dim3(M_TOTAL * D_MODEL / 1024, 1, 3), 256>>>(query, key, value);
    prep_w <<<dim3(D_MODEL * D_MODEL / 1024, 1, 4), 256>>>(Wq, Wk, Wv, Wo);
    qkv_kernel<<<dim3(D_MODEL / 64, M_TOTAL / 128, 3), 256>>>(bq, bk, bv);
    attn_kernel<<<dim3(SEQ / 64, BATCH * N_HEADS), 128>>>();
    out_kernel<<<dim3(D_MODEL / 64, M_TOTAL / 128), 256>>>(bo, out);
}